// round 14
// baseline (speedup 1.0000x reference)
#include <cuda_runtime.h>
#include <math.h>

#define DIM     512
#define CDIM    14
#define KSIZE   16384
#define NBLK    256      // 8192 tokens / 32 per block
#define WOPITCH 520      // padded s_wout row pitch
#define NSPIN   64       // last-N finishers do phase 2
#define THRESH  (NBLK - NSPIN)

// scratch — static device globals (no allocation allowed)
__device__ float g_part[NBLK * KSIZE];   // per-block partial prob sums (16MB)
__device__ float g_sc[NBLK];             // per-block commit partial
__device__ float g_se[NBLK];             // per-block sample-entropy partial
__device__ float g_hc[NSPIN];            // per-chunk codebook-entropy partial
__device__ int   g_done1;                // phase-1 ticket counter (self-resetting)
__device__ int   g_done2;                // phase-2 finisher counter (self-resetting)

#define PACK2(d, x, y)   asm("mov.b64 %0, {%1, %2};" : "=l"(d) : "f"(x), "f"(y))
#define UNPACK2(x, y, d) asm("mov.b64 {%0, %1}, %2;" : "=f"(x), "=f"(y) : "l"(d))
#define FMA2(acc, a, b)  asm("fma.rn.f32x2 %0, %1, %2, %0;" : "+l"(acc) : "l"(a), "l"(b))
#define ADD4(a, b)       do { (a).x += (b).x; (a).y += (b).y; (a).z += (b).z; (a).w += (b).w; } while (0)

// ---------------------------------------------------------------- fused kernel
// grid = 256 blocks x 256 threads; block owns 32 tokens (4 per warp).
// Phase 2 (avg-prob reduction + aux) is done by the LAST 64 blocks to finish
// phase 1 — deadlock-free under any scheduling (early blocks exit and free SMs).
__global__ __launch_bounds__(256, 2) void kF(
    const float* __restrict__ x,
    const float* __restrict__ w_in,   // [14][512]
    const float* __restrict__ b_in,   // [14]
    const float* __restrict__ w_out,  // [512][14]
    const float* __restrict__ b_out,  // [512]
    float* __restrict__ out,
    float* __restrict__ idx_out,
    float* __restrict__ aux_out,
    float inv_ntok)
{
    // blob: stage A = s_wout (7280 used); stage C = tA|tB (8192);
    //       phase 2 = 256-float4 staging (1024 floats)
    __shared__ __align__(16) float blob[8192];
    __shared__ float s_bin[16];
    __shared__ float sQ[32 * 16];              // p, then sigmoid(p) in place
    __shared__ float sred[16];
    __shared__ int   s_ticket;
    __shared__ int   lastflag;

    float* s_wout = blob;
    float* tA = blob;
    float* tB = blob + 4096;

    int tid = threadIdx.x;
    for (int i = tid; i < CDIM * DIM; i += 256) {
        int d = i / CDIM, c = i % CDIM;
        s_wout[c * WOPITCH + d] = w_out[i];
    }
    if (tid < CDIM) s_bin[tid] = b_in[tid];
    __syncthreads();

    int w = tid >> 5, l = tid & 31;
    const float4* win4  = (const float4*)w_in;
    const float4* wout4 = (const float4*)s_wout;   // row stride 130 float4
    const float4* bout4 = (const float4*)b_out;

    int tok0   = w * 4;
    int token0 = blockIdx.x * 32 + tok0;

    // ---- stage A part 1: projection, 4 tokens jointly, k-outer
    float s0[CDIM], s1[CDIM], s2[CDIM], s3[CDIM];
    #pragma unroll
    for (int c = 0; c < CDIM; c++) { s0[c]=0.f; s1[c]=0.f; s2[c]=0.f; s3[c]=0.f; }

    #pragma unroll
    for (int k = 0; k < 4; k++) {
        float4 xv0 = ((const float4*)(x + (size_t)(token0    ) * DIM))[k * 32 + l];
        float4 xv1 = ((const float4*)(x + (size_t)(token0 + 1) * DIM))[k * 32 + l];
        float4 xv2 = ((const float4*)(x + (size_t)(token0 + 2) * DIM))[k * 32 + l];
        float4 xv3 = ((const float4*)(x + (size_t)(token0 + 3) * DIM))[k * 32 + l];
        #pragma unroll
        for (int c = 0; c < CDIM; c++) {
            float4 wv = win4[c * 128 + k * 32 + l];
            s0[c] += xv0.x*wv.x + xv0.y*wv.y + xv0.z*wv.z + xv0.w*wv.w;
            s1[c] += xv1.x*wv.x + xv1.y*wv.y + xv1.z*wv.z + xv1.w*wv.w;
            s2[c] += xv2.x*wv.x + xv2.y*wv.y + xv2.z*wv.z + xv2.w*wv.w;
            s3[c] += xv3.x*wv.x + xv3.y*wv.y + xv3.z*wv.z + xv3.w*wv.w;
        }
    }

    // fold reduction: lane group g = l>>3 ends owning token g.
    float pv[CDIM];
    #pragma unroll
    for (int c = 0; c < CDIM; c++) {
        float t0 = s0[c], t1 = s1[c], t2 = s2[c], t3 = s3[c];
        t0 += __shfl_xor_sync(0xffffffffu, t0, 16);
        t1 += __shfl_xor_sync(0xffffffffu, t1, 16);
        t2 += __shfl_xor_sync(0xffffffffu, t2, 16);
        t3 += __shfl_xor_sync(0xffffffffu, t3, 16);
        float a = (l < 16) ? t0 : t2;
        float b = (l < 16) ? t1 : t3;
        a += __shfl_xor_sync(0xffffffffu, a, 8);
        b += __shfl_xor_sync(0xffffffffu, b, 8);
        float m = (l & 8) ? b : a;
        m += __shfl_xor_sync(0xffffffffu, m, 4);
        m += __shfl_xor_sync(0xffffffffu, m, 2);
        m += __shfl_xor_sync(0xffffffffu, m, 1);
        pv[c] = m + s_bin[c];
    }

    int g = l >> 3;
    unsigned idx = 0;
    float commit = 0.f;
    #pragma unroll
    for (int c = 0; c < CDIM; c++) {
        bool pos = pv[c] > 0.f;
        idx |= (pos ? 1u : 0u) << (13 - c);
        float sg = pos ? 1.f : -1.f;
        float d = pv[c] - sg;
        commit += d * d;
    }
    if ((l & 7) == 0) {
        idx_out[token0 + g] = (float)idx;
        #pragma unroll
        for (int c = 0; c < CDIM; c++) sQ[(tok0 + g) * 16 + c] = pv[c];
    }

    unsigned idxs[4];
    #pragma unroll
    for (int t = 0; t < 4; t++) idxs[t] = __shfl_sync(0xffffffffu, idx, t * 8);
    commit += __shfl_xor_sync(0xffffffffu, commit, 8);
    commit += __shfl_xor_sync(0xffffffffu, commit, 16);
    float commit_acc = commit;

    float sg[4][CDIM];
    #pragma unroll
    for (int t = 0; t < 4; t++)
        #pragma unroll
        for (int c = 0; c < CDIM; c++)
            sg[t][c] = ((idxs[t] >> (13 - c)) & 1) ? 1.f : -1.f;

    // ---- stage A part 2: project-out, 4 tokens jointly, k-outer
    #pragma unroll
    for (int k = 0; k < 4; k++) {
        float4 bb = bout4[k * 32 + l];
        float4 a[4];
        #pragma unroll
        for (int t = 0; t < 4; t++) a[t] = bb;
        #pragma unroll
        for (int c = 0; c < CDIM; c++) {
            float4 wv = wout4[c * 130 + k * 32 + l];
            #pragma unroll
            for (int t = 0; t < 4; t++) {
                a[t].x += sg[t][c] * wv.x; a[t].y += sg[t][c] * wv.y;
                a[t].z += sg[t][c] * wv.z; a[t].w += sg[t][c] * wv.w;
            }
        }
        #pragma unroll
        for (int t = 0; t < 4; t++)
            ((float4*)(out + (size_t)(token0 + t) * DIM))[k * 32 + l] = a[t];
    }
    __syncthreads();

    // ---- stage B: sigmoids (in place) + per-sample entropy partial
    float hloc = 0.f;
    for (int i = tid; i < 32 * CDIM; i += 256) {
        int tok = i / CDIM, c = i % CDIM;
        float p = sQ[tok * 16 + c];
        float q = 1.f / (1.f + __expf(-400.f * p));
        sQ[tok * 16 + c] = q;
        float qm = 1.f - q;
        hloc += -(q  * __logf(fmaxf(q,  1e-20f)) +
                  qm * __logf(fmaxf(qm, 1e-20f)));
    }
    __syncthreads();    // q ready; s_wout dead -> blob becomes tables

    // ---- stage C build: all 32 token tables, one pass
    #pragma unroll 1
    for (int t = 0; t < 32; t++) {
        const float4* q4 = (const float4*)&sQ[t * 16];
        if (tid < 128) {                       // A over c = 0..6 (bits 13..7)
            float4 qa = q4[0], qb = q4[1];
            float v = ((tid & 64) ? qa.x : 1.f - qa.x)
                    * ((tid & 32) ? qa.y : 1.f - qa.y)
                    * ((tid & 16) ? qa.z : 1.f - qa.z)
                    * ((tid &  8) ? qa.w : 1.f - qa.w)
                    * ((tid &  4) ? qb.x : 1.f - qb.x)
                    * ((tid &  2) ? qb.y : 1.f - qb.y)
                    * ((tid &  1) ? qb.z : 1.f - qb.z);
            tA[t * 128 + tid] = v;
        } else {                               // B over c = 7..13 (bits 6..0)
            int lo = tid - 128;
            float4 qb = q4[1], qc = q4[2], qd = q4[3];
            float v = ((lo & 64) ? qb.w : 1.f - qb.w)
                    * ((lo & 32) ? qc.x : 1.f - qc.x)
                    * ((lo & 16) ? qc.y : 1.f - qc.y)
                    * ((lo &  8) ? qc.z : 1.f - qc.z)
                    * ((lo &  4) ? qc.w : 1.f - qc.w)
                    * ((lo &  2) ? qd.x : 1.f - qd.x)
                    * ((lo &  1) ? qd.y : 1.f - qd.y);
            tB[t * 128 + lo] = v;
        }
    }
    __syncthreads();

    // ---- stage C consume: barrier-free packed-FFMA2 stream
    unsigned long long acc2[32];
    #pragma unroll
    for (int i = 0; i < 32; i++) acc2[i] = 0ull;

    #pragma unroll 2
    for (int t = 0; t < 32; t++) {
        float4 bv = ((const float4*)&tB[t * 128])[l];         // lane-varying
        unsigned long long bd0, bd1, bd2, bd3;
        PACK2(bd0, bv.x, bv.x); PACK2(bd1, bv.y, bv.y);
        PACK2(bd2, bv.z, bv.z); PACK2(bd3, bv.w, bv.w);
        const float4* ap = (const float4*)&tA[t * 128 + w * 16]; // broadcast
        #pragma unroll
        for (int i2g = 0; i2g < 4; i2g++) {
            float4 aa = ap[i2g];
            unsigned long long ad0, ad1;
            PACK2(ad0, aa.x, aa.y);
            PACK2(ad1, aa.z, aa.w);
            int base = i2g * 8;
            FMA2(acc2[base + 0], ad0, bd0);
            FMA2(acc2[base + 1], ad0, bd1);
            FMA2(acc2[base + 2], ad0, bd2);
            FMA2(acc2[base + 3], ad0, bd3);
            FMA2(acc2[base + 4], ad1, bd0);
            FMA2(acc2[base + 5], ad1, bd1);
            FMA2(acc2[base + 6], ad1, bd2);
            FMA2(acc2[base + 7], ad1, bd3);
        }
    }

    // ---- epilogue: unpack + coalesced writes (code j = w*2048 + i*128 + l*4 + k)
    float4* dst = (float4*)(g_part + (size_t)blockIdx.x * KSIZE + w * 2048);
    #pragma unroll
    for (int i2 = 0; i2 < 8; i2++) {
        float lo0, hi0, lo1, hi1, lo2, hi2, lo3, hi3;
        UNPACK2(lo0, hi0, acc2[i2 * 4 + 0]);
        UNPACK2(lo1, hi1, acc2[i2 * 4 + 1]);
        UNPACK2(lo2, hi2, acc2[i2 * 4 + 2]);
        UNPACK2(lo3, hi3, acc2[i2 * 4 + 3]);
        dst[(2 * i2    ) * 32 + l] = make_float4(lo0, lo1, lo2, lo3);
        dst[(2 * i2 + 1) * 32 + l] = make_float4(hi0, hi1, hi2, hi3);
    }

    // ---- block scalar partials
    #pragma unroll
    for (int off = 16; off; off >>= 1) hloc += __shfl_xor_sync(0xffffffffu, hloc, off);
    if (l == 0) { sred[w] = commit_acc; sred[8 + w] = hloc; }
    __syncthreads();
    if (tid == 0) {
        float c = 0.f, h = 0.f;
        #pragma unroll
        for (int i = 0; i < 8; i++) { c += sred[i]; h += sred[8 + i]; }
        g_sc[blockIdx.x] = c;
        g_se[blockIdx.x] = h;
    }

    // ================= ticket: last-64 finishers do phase 2 =================
    __threadfence();                      // release phase-1 writes
    if (tid == 0) s_ticket = atomicAdd(&g_done1, 1);   // 0..255
    __syncthreads();
    int ticket = s_ticket;
    if (ticket < THRESH) return;          // early blocks exit, freeing SMs

    if (tid == 0) {                       // spin until all 256 finished phase 1
        volatile int* vd = &g_done1;
        while (*vd < NBLK) __nanosleep(64);
    }
    __syncthreads();
    __threadfence();                      // acquire: all g_part/g_sc/g_se visible

    // ---- phase 2: chunk ch owns codes [ch*256, ch*256+256) = 64 quads
    int ch = ticket - THRESH;             // 0..63
    {
        float4* blob4 = (float4*)blob;    // staging: [h*64 + qloc]
        int qloc = tid & 63;
        int h    = tid >> 6;              // 0..3, 64 partials each
        const float4* p4 = (const float4*)g_part;   // [partial*4096 + quad]
        size_t b0 = (size_t)(h * 64) * 4096 + (size_t)ch * 64 + qloc;

        float4 a0 = make_float4(0,0,0,0), a1 = a0, a2 = a0, a3 = a0,
               a4 = a0, a5 = a0, a6 = a0, a7 = a0;
        #pragma unroll
        for (int j = 0; j < 64; j += 8) {
            float4 v0 = p4[b0 + (size_t)(j    ) * 4096];
            float4 v1 = p4[b0 + (size_t)(j + 1) * 4096];
            float4 v2 = p4[b0 + (size_t)(j + 2) * 4096];
            float4 v3 = p4[b0 + (size_t)(j + 3) * 4096];
            float4 v4 = p4[b0 + (size_t)(j + 4) * 4096];
            float4 v5 = p4[b0 + (size_t)(j + 5) * 4096];
            float4 v6 = p4[b0 + (size_t)(j + 6) * 4096];
            float4 v7 = p4[b0 + (size_t)(j + 7) * 4096];
            ADD4(a0, v0); ADD4(a1, v1); ADD4(a2, v2); ADD4(a3, v3);
            ADD4(a4, v4); ADD4(a5, v5); ADD4(a6, v6); ADD4(a7, v7);
        }
        ADD4(a0, a1); ADD4(a2, a3); ADD4(a4, a5); ADD4(a6, a7);
        ADD4(a0, a2); ADD4(a4, a6); ADD4(a0, a4);
        blob4[h * 64 + qloc] = a0;
        __syncthreads();

        if (tid < 64) {
            float4 t0 = blob4[tid], t1 = blob4[64 + tid],
                   t2 = blob4[128 + tid], t3 = blob4[192 + tid];
            ADD4(t0, t1); ADD4(t2, t3); ADD4(t0, t2);
            float ax = t0.x * inv_ntok, ay = t0.y * inv_ntok,
                  az = t0.z * inv_ntok, aw = t0.w * inv_ntok;
            float s = -(ax * __logf(fmaxf(ax, 1e-20f))
                      + ay * __logf(fmaxf(ay, 1e-20f))
                      + az * __logf(fmaxf(az, 1e-20f))
                      + aw * __logf(fmaxf(aw, 1e-20f)));
            #pragma unroll
            for (int off = 16; off; off >>= 1) s += __shfl_xor_sync(0xffffffffu, s, off);
            if ((tid & 31) == 0) sred[tid >> 5] = s;
        }
        __syncthreads();
        if (tid == 0) g_hc[ch] = sred[0] + sred[1];
    }

    // ---- finisher: last of the 64 combines scalars, resets counters
    __threadfence();
    if (tid == 0) lastflag = (atomicAdd(&g_done2, 1) == NSPIN - 1);
    __syncthreads();
    if (lastflag) {
        float hc = (tid < NSPIN) ? g_hc[tid] : 0.f;
        float sc = g_sc[tid];
        float se = g_se[tid];
        #pragma unroll
        for (int off = 16; off; off >>= 1) {
            hc += __shfl_xor_sync(0xffffffffu, hc, off);
            sc += __shfl_xor_sync(0xffffffffu, sc, off);
            se += __shfl_xor_sync(0xffffffffu, se, off);
        }
        __shared__ float sr[3][8];
        if ((tid & 31) == 0) { sr[0][w] = hc; sr[1][w] = sc; sr[2][w] = se; }
        __syncthreads();
        if (tid == 0) {
            float Hc = 0.f, C = 0.f, Hs = 0.f;
            #pragma unroll
            for (int i = 0; i < 8; i++) { Hc += sr[0][i]; C += sr[1][i]; Hs += sr[2][i]; }
            float per_sample = Hs * inv_ntok;
            float commitm = C * inv_ntok * (1.f / (float)CDIM);
            *aux_out = 0.1f * (per_sample - Hc) + 0.25f * commitm;
            g_done1 = 0;                  // reset for next launch/replay
            g_done2 = 0;
        }
    }
}

// ----------------------------------------------------------------
extern "C" void kernel_launch(void* const* d_in, const int* in_sizes, int n_in,
                              void* d_out, int out_size) {
    const float* x     = (const float*)d_in[0];
    const float* w_in  = (const float*)d_in[1];
    const float* b_in  = (const float*)d_in[2];
    const float* w_out = (const float*)d_in[3];
    const float* b_out = (const float*)d_in[4];

    int ntok = in_sizes[0] / DIM;               // 8192
    float* out     = (float*)d_out;
    float* idx_out = out + (size_t)ntok * DIM;
    float* aux_out = idx_out + ntok;

    kF<<<ntok / 32, 256>>>(x, w_in, b_in, w_out, b_out, out, idx_out,
                           aux_out, 1.f / (float)ntok);
}

// round 15
// speedup vs baseline: 1.0073x; 1.0073x over previous
#include <cuda_runtime.h>
#include <cuda_fp16.h>
#include <math.h>

#define DIM     512
#define CDIM    14
#define KSIZE   16384
#define NBLK    256      // 8192 tokens / 32 per block
#define WOPITCH 520      // padded s_wout row pitch
#define NSPIN   128      // last-N finishers do phase 2
#define THRESH  (NBLK - NSPIN)

// scratch — static device globals (no allocation allowed)
__device__ uint2 g_parth[NBLK * 4096];   // per-block partial prob sums, half2x2 (8MB)
__device__ float g_sc[NBLK];             // per-block commit partial
__device__ float g_se[NBLK];             // per-block sample-entropy partial
__device__ float g_hc[NSPIN];            // per-chunk codebook-entropy partial
__device__ int   g_done1;                // phase-1 ticket counter (self-resetting)
__device__ int   g_done2;                // phase-2 finisher counter (self-resetting)

#define PACK2(d, x, y)   asm("mov.b64 %0, {%1, %2};" : "=l"(d) : "f"(x), "f"(y))
#define UNPACK2(x, y, d) asm("mov.b64 {%0, %1}, %2;" : "=f"(x), "=f"(y) : "l"(d))
#define FMA2(acc, a, b)  asm("fma.rn.f32x2 %0, %1, %2, %0;" : "+l"(acc) : "l"(a), "l"(b))
#define ADD4(a, b)       do { (a).x += (b).x; (a).y += (b).y; (a).z += (b).z; (a).w += (b).w; } while (0)

static __device__ __forceinline__ unsigned pack_h2(float a, float b) {
    __half2 h = __floats2half2_rn(a, b);
    return *reinterpret_cast<unsigned*>(&h);
}
static __device__ __forceinline__ float2 unpack_h2(unsigned u) {
    __half2 h = *reinterpret_cast<__half2*>(&u);
    return __half22float2(h);
}

// ---------------------------------------------------------------- fused kernel
// grid = 256 blocks x 256 threads; block owns 32 tokens (4 per warp).
// Phase 2 (avg-prob reduction + aux) is done by the LAST 128 blocks to finish
// phase 1 — deadlock-free under any scheduling (early blocks exit, freeing SMs;
// spinners (<=128) < SM count, so unscheduled blocks can always run).
__global__ __launch_bounds__(256, 2) void kF(
    const float* __restrict__ x,
    const float* __restrict__ w_in,   // [14][512]
    const float* __restrict__ b_in,   // [14]
    const float* __restrict__ w_out,  // [512][14]
    const float* __restrict__ b_out,  // [512]
    float* __restrict__ out,
    float* __restrict__ idx_out,
    float* __restrict__ aux_out,
    float inv_ntok)
{
    // blob: stage A = s_wout (7280 used); stage C = tA|tB (8192);
    //       phase 2 = 256-float4 staging
    __shared__ __align__(16) float blob[8192];
    __shared__ float s_bin[16];
    __shared__ float sQ[32 * 16];              // p, then sigmoid(p) in place
    __shared__ float sred[16];
    __shared__ int   s_ticket;
    __shared__ int   lastflag;

    float* s_wout = blob;
    float* tA = blob;
    float* tB = blob + 4096;

    int tid = threadIdx.x;
    for (int i = tid; i < CDIM * DIM; i += 256) {
        int d = i / CDIM, c = i % CDIM;
        s_wout[c * WOPITCH + d] = w_out[i];
    }
    if (tid < CDIM) s_bin[tid] = b_in[tid];
    __syncthreads();

    int w = tid >> 5, l = tid & 31;
    const float4* win4  = (const float4*)w_in;
    const float4* wout4 = (const float4*)s_wout;   // row stride 130 float4
    const float4* bout4 = (const float4*)b_out;

    int tok0   = w * 4;
    int token0 = blockIdx.x * 32 + tok0;

    // ---- stage A part 1: projection, 4 tokens jointly, k-outer
    float s0[CDIM], s1[CDIM], s2[CDIM], s3[CDIM];
    #pragma unroll
    for (int c = 0; c < CDIM; c++) { s0[c]=0.f; s1[c]=0.f; s2[c]=0.f; s3[c]=0.f; }

    #pragma unroll
    for (int k = 0; k < 4; k++) {
        float4 xv0 = ((const float4*)(x + (size_t)(token0    ) * DIM))[k * 32 + l];
        float4 xv1 = ((const float4*)(x + (size_t)(token0 + 1) * DIM))[k * 32 + l];
        float4 xv2 = ((const float4*)(x + (size_t)(token0 + 2) * DIM))[k * 32 + l];
        float4 xv3 = ((const float4*)(x + (size_t)(token0 + 3) * DIM))[k * 32 + l];
        #pragma unroll
        for (int c = 0; c < CDIM; c++) {
            float4 wv = win4[c * 128 + k * 32 + l];
            s0[c] += xv0.x*wv.x + xv0.y*wv.y + xv0.z*wv.z + xv0.w*wv.w;
            s1[c] += xv1.x*wv.x + xv1.y*wv.y + xv1.z*wv.z + xv1.w*wv.w;
            s2[c] += xv2.x*wv.x + xv2.y*wv.y + xv2.z*wv.z + xv2.w*wv.w;
            s3[c] += xv3.x*wv.x + xv3.y*wv.y + xv3.z*wv.z + xv3.w*wv.w;
        }
    }

    // fold reduction: lane group g = l>>3 ends owning token g.
    float pv[CDIM];
    #pragma unroll
    for (int c = 0; c < CDIM; c++) {
        float t0 = s0[c], t1 = s1[c], t2 = s2[c], t3 = s3[c];
        t0 += __shfl_xor_sync(0xffffffffu, t0, 16);
        t1 += __shfl_xor_sync(0xffffffffu, t1, 16);
        t2 += __shfl_xor_sync(0xffffffffu, t2, 16);
        t3 += __shfl_xor_sync(0xffffffffu, t3, 16);
        float a = (l < 16) ? t0 : t2;
        float b = (l < 16) ? t1 : t3;
        a += __shfl_xor_sync(0xffffffffu, a, 8);
        b += __shfl_xor_sync(0xffffffffu, b, 8);
        float m = (l & 8) ? b : a;
        m += __shfl_xor_sync(0xffffffffu, m, 4);
        m += __shfl_xor_sync(0xffffffffu, m, 2);
        m += __shfl_xor_sync(0xffffffffu, m, 1);
        pv[c] = m + s_bin[c];
    }

    int g = l >> 3;
    unsigned idx = 0;
    float commit = 0.f;
    #pragma unroll
    for (int c = 0; c < CDIM; c++) {
        bool pos = pv[c] > 0.f;
        idx |= (pos ? 1u : 0u) << (13 - c);
        float sg = pos ? 1.f : -1.f;
        float d = pv[c] - sg;
        commit += d * d;
    }
    if ((l & 7) == 0) {
        idx_out[token0 + g] = (float)idx;
        #pragma unroll
        for (int c = 0; c < CDIM; c++) sQ[(tok0 + g) * 16 + c] = pv[c];
    }

    unsigned idxs[4];
    #pragma unroll
    for (int t = 0; t < 4; t++) idxs[t] = __shfl_sync(0xffffffffu, idx, t * 8);
    commit += __shfl_xor_sync(0xffffffffu, commit, 8);
    commit += __shfl_xor_sync(0xffffffffu, commit, 16);
    float commit_acc = commit;

    float sg[4][CDIM];
    #pragma unroll
    for (int t = 0; t < 4; t++)
        #pragma unroll
        for (int c = 0; c < CDIM; c++)
            sg[t][c] = ((idxs[t] >> (13 - c)) & 1) ? 1.f : -1.f;

    // ---- stage A part 2: project-out, 4 tokens jointly, k-outer
    #pragma unroll
    for (int k = 0; k < 4; k++) {
        float4 bb = bout4[k * 32 + l];
        float4 a[4];
        #pragma unroll
        for (int t = 0; t < 4; t++) a[t] = bb;
        #pragma unroll
        for (int c = 0; c < CDIM; c++) {
            float4 wv = wout4[c * 130 + k * 32 + l];
            #pragma unroll
            for (int t = 0; t < 4; t++) {
                a[t].x += sg[t][c] * wv.x; a[t].y += sg[t][c] * wv.y;
                a[t].z += sg[t][c] * wv.z; a[t].w += sg[t][c] * wv.w;
            }
        }
        #pragma unroll
        for (int t = 0; t < 4; t++)
            ((float4*)(out + (size_t)(token0 + t) * DIM))[k * 32 + l] = a[t];
    }
    __syncthreads();

    // ---- stage B: sigmoids (in place) + per-sample entropy partial
    float hloc = 0.f;
    for (int i = tid; i < 32 * CDIM; i += 256) {
        int tok = i / CDIM, c = i % CDIM;
        float p = sQ[tok * 16 + c];
        float q = 1.f / (1.f + __expf(-400.f * p));
        sQ[tok * 16 + c] = q;
        float qm = 1.f - q;
        hloc += -(q  * __logf(fmaxf(q,  1e-20f)) +
                  qm * __logf(fmaxf(qm, 1e-20f)));
    }
    __syncthreads();    // q ready; s_wout dead -> blob becomes tables

    // ---- stage C build: all 32 token tables, one pass
    #pragma unroll 1
    for (int t = 0; t < 32; t++) {
        const float4* q4 = (const float4*)&sQ[t * 16];
        if (tid < 128) {                       // A over c = 0..6 (bits 13..7)
            float4 qa = q4[0], qb = q4[1];
            float v = ((tid & 64) ? qa.x : 1.f - qa.x)
                    * ((tid & 32) ? qa.y : 1.f - qa.y)
                    * ((tid & 16) ? qa.z : 1.f - qa.z)
                    * ((tid &  8) ? qa.w : 1.f - qa.w)
                    * ((tid &  4) ? qb.x : 1.f - qb.x)
                    * ((tid &  2) ? qb.y : 1.f - qb.y)
                    * ((tid &  1) ? qb.z : 1.f - qb.z);
            tA[t * 128 + tid] = v;
        } else {                               // B over c = 7..13 (bits 6..0)
            int lo = tid - 128;
            float4 qb = q4[1], qc = q4[2], qd = q4[3];
            float v = ((lo & 64) ? qb.w : 1.f - qb.w)
                    * ((lo & 32) ? qc.x : 1.f - qc.x)
                    * ((lo & 16) ? qc.y : 1.f - qc.y)
                    * ((lo &  8) ? qc.z : 1.f - qc.z)
                    * ((lo &  4) ? qc.w : 1.f - qc.w)
                    * ((lo &  2) ? qd.x : 1.f - qd.x)
                    * ((lo &  1) ? qd.y : 1.f - qd.y);
            tB[t * 128 + lo] = v;
        }
    }
    __syncthreads();

    // ---- stage C consume: barrier-free packed-FFMA2 stream
    unsigned long long acc2[32];
    #pragma unroll
    for (int i = 0; i < 32; i++) acc2[i] = 0ull;

    #pragma unroll 2
    for (int t = 0; t < 32; t++) {
        float4 bv = ((const float4*)&tB[t * 128])[l];         // lane-varying
        unsigned long long bd0, bd1, bd2, bd3;
        PACK2(bd0, bv.x, bv.x); PACK2(bd1, bv.y, bv.y);
        PACK2(bd2, bv.z, bv.z); PACK2(bd3, bv.w, bv.w);
        const float4* ap = (const float4*)&tA[t * 128 + w * 16]; // broadcast
        #pragma unroll
        for (int i2g = 0; i2g < 4; i2g++) {
            float4 aa = ap[i2g];
            unsigned long long ad0, ad1;
            PACK2(ad0, aa.x, aa.y);
            PACK2(ad1, aa.z, aa.w);
            int base = i2g * 8;
            FMA2(acc2[base + 0], ad0, bd0);
            FMA2(acc2[base + 1], ad0, bd1);
            FMA2(acc2[base + 2], ad0, bd2);
            FMA2(acc2[base + 3], ad0, bd3);
            FMA2(acc2[base + 4], ad1, bd0);
            FMA2(acc2[base + 5], ad1, bd1);
            FMA2(acc2[base + 6], ad1, bd2);
            FMA2(acc2[base + 7], ad1, bd3);
        }
    }

    // ---- epilogue: half2 partial writes.
    // Code j = w*2048 + r*128 + l*4 + k; uint2 slot j/4 = w*512 + r*32 + l.
    // acc2[i2*4+k] lanes = rows (2*i2, 2*i2+1) of this warp's 16 rows.
    {
        uint2* dsth = g_parth + (size_t)blockIdx.x * 4096 + w * 512;
        #pragma unroll
        for (int i2 = 0; i2 < 8; i2++) {
            float lo0, hi0, lo1, hi1, lo2, hi2, lo3, hi3;
            UNPACK2(lo0, hi0, acc2[i2 * 4 + 0]);
            UNPACK2(lo1, hi1, acc2[i2 * 4 + 1]);
            UNPACK2(lo2, hi2, acc2[i2 * 4 + 2]);
            UNPACK2(lo3, hi3, acc2[i2 * 4 + 3]);
            uint2 ulo, uhi;
            ulo.x = pack_h2(lo0, lo1); ulo.y = pack_h2(lo2, lo3);
            uhi.x = pack_h2(hi0, hi1); uhi.y = pack_h2(hi2, hi3);
            dsth[(2 * i2    ) * 32 + l] = ulo;
            dsth[(2 * i2 + 1) * 32 + l] = uhi;
        }
    }

    // ---- block scalar partials
    #pragma unroll
    for (int off = 16; off; off >>= 1) hloc += __shfl_xor_sync(0xffffffffu, hloc, off);
    if (l == 0) { sred[w] = commit_acc; sred[8 + w] = hloc; }
    __syncthreads();
    if (tid == 0) {
        float c = 0.f, h = 0.f;
        #pragma unroll
        for (int i = 0; i < 8; i++) { c += sred[i]; h += sred[8 + i]; }
        g_sc[blockIdx.x] = c;
        g_se[blockIdx.x] = h;
    }

    // ================= ticket: last-128 finishers do phase 2 =================
    __threadfence();                      // release phase-1 writes
    if (tid == 0) s_ticket = atomicAdd(&g_done1, 1);   // 0..255
    __syncthreads();
    int ticket = s_ticket;
    if (ticket < THRESH) return;          // early blocks exit, freeing SMs

    if (tid == 0) {                       // spin until all 256 finished phase 1
        volatile int* vd = &g_done1;
        while (*vd < NBLK) __nanosleep(64);
    }
    __syncthreads();
    __threadfence();                      // acquire: all partials visible

    // ---- phase 2: chunk ch owns codes [ch*128, ch*128+128) = 32 uint2 groups
    int ch = ticket - THRESH;             // 0..127
    {
        float4* blob4 = (float4*)blob;    // staging: [h*32 + qloc]
        int qloc = tid & 31;              // uint2 group (4 codes)
        int h    = tid >> 5;              // 0..7, 32 partials each
        const uint2* ph = g_parth;        // [partial*4096 + group]
        size_t b0 = (size_t)(h * 32) * 4096 + (size_t)ch * 32 + qloc;

        float4 a0 = make_float4(0,0,0,0), a1 = a0, a2 = a0, a3 = a0;
        #pragma unroll
        for (int j = 0; j < 32; j += 4) {
            uint2 u0 = ph[b0 + (size_t)(j    ) * 4096];
            uint2 u1 = ph[b0 + (size_t)(j + 1) * 4096];
            uint2 u2 = ph[b0 + (size_t)(j + 2) * 4096];
            uint2 u3 = ph[b0 + (size_t)(j + 3) * 4096];
            float2 f0a = unpack_h2(u0.x), f0b = unpack_h2(u0.y);
            float2 f1a = unpack_h2(u1.x), f1b = unpack_h2(u1.y);
            float2 f2a = unpack_h2(u2.x), f2b = unpack_h2(u2.y);
            float2 f3a = unpack_h2(u3.x), f3b = unpack_h2(u3.y);
            a0.x += f0a.x; a0.y += f0a.y; a0.z += f0b.x; a0.w += f0b.y;
            a1.x += f1a.x; a1.y += f1a.y; a1.z += f1b.x; a1.w += f1b.y;
            a2.x += f2a.x; a2.y += f2a.y; a2.z += f2b.x; a2.w += f2b.y;
            a3.x += f3a.x; a3.y += f3a.y; a3.z += f3b.x; a3.w += f3b.y;
        }
        ADD4(a0, a1); ADD4(a2, a3); ADD4(a0, a2);
        blob4[h * 32 + qloc] = a0;
        __syncthreads();

        if (tid < 32) {
            float4 t0 = blob4[tid];
            #pragma unroll
            for (int hh = 1; hh < 8; hh++) { float4 tt = blob4[hh * 32 + tid]; ADD4(t0, tt); }
            float ax = t0.x * inv_ntok, ay = t0.y * inv_ntok,
                  az = t0.z * inv_ntok, aw = t0.w * inv_ntok;
            float s = -(ax * __logf(fmaxf(ax, 1e-20f))
                      + ay * __logf(fmaxf(ay, 1e-20f))
                      + az * __logf(fmaxf(az, 1e-20f))
                      + aw * __logf(fmaxf(aw, 1e-20f)));
            #pragma unroll
            for (int off = 16; off; off >>= 1) s += __shfl_xor_sync(0xffffffffu, s, off);
            if (tid == 0) g_hc[ch] = s;
        }
    }

    // ---- finisher: last of the 128 combines scalars, resets counters
    __threadfence();
    if (tid == 0) lastflag = (atomicAdd(&g_done2, 1) == NSPIN - 1);
    __syncthreads();
    if (lastflag) {
        float hc = (tid < NSPIN) ? g_hc[tid] : 0.f;
        float sc = g_sc[tid];
        float se = g_se[tid];
        #pragma unroll
        for (int off = 16; off; off >>= 1) {
            hc += __shfl_xor_sync(0xffffffffu, hc, off);
            sc += __shfl_xor_sync(0xffffffffu, sc, off);
            se += __shfl_xor_sync(0xffffffffu, se, off);
        }
        __shared__ float sr[3][8];
        if ((tid & 31) == 0) { sr[0][w] = hc; sr[1][w] = sc; sr[2][w] = se; }
        __syncthreads();
        if (tid == 0) {
            float Hc = 0.f, C = 0.f, Hs = 0.f;
            #pragma unroll
            for (int i = 0; i < 8; i++) { Hc += sr[0][i]; C += sr[1][i]; Hs += sr[2][i]; }
            float per_sample = Hs * inv_ntok;
            float commitm = C * inv_ntok * (1.f / (float)CDIM);
            *aux_out = 0.1f * (per_sample - Hc) + 0.25f * commitm;
            g_done1 = 0;                  // reset for next launch/replay
            g_done2 = 0;
        }
    }
}

// ----------------------------------------------------------------
extern "C" void kernel_launch(void* const* d_in, const int* in_sizes, int n_in,
                              void* d_out, int out_size) {
    const float* x     = (const float*)d_in[0];
    const float* w_in  = (const float*)d_in[1];
    const float* b_in  = (const float*)d_in[2];
    const float* w_out = (const float*)d_in[3];
    const float* b_out = (const float*)d_in[4];

    int ntok = in_sizes[0] / DIM;               // 8192
    float* out     = (float*)d_out;
    float* idx_out = out + (size_t)ntok * DIM;
    float* aux_out = idx_out + ntok;

    kF<<<ntok / 32, 256>>>(x, w_in, b_in, w_out, b_out, out, idx_out,
                           aux_out, 1.f / (float)ntok);
}

// round 16
// speedup vs baseline: 1.0733x; 1.0656x over previous
#include <cuda_runtime.h>
#include <cuda_fp16.h>
#include <math.h>

#define DIM     512
#define CDIM    14
#define KSIZE   16384
#define NBLK    256      // 8192 tokens / 32 per block
#define WOPITCH 520      // padded s_wout row pitch
#define R3BLK   512      // k3 grid

// scratch — static device globals (no allocation allowed)
__device__ uint2 g_parth[NBLK * 4096];   // per-block partial prob sums, half2x2 (8MB)
__device__ float g_sc[NBLK];             // per-block commit partial
__device__ float g_se[NBLK];             // per-block sample-entropy partial
__device__ float g_hc[R3BLK];            // per-k3-block codebook-entropy partial
__device__ int   g_done;                 // finisher counter (self-resetting)

#define PACK2(d, x, y)   asm("mov.b64 %0, {%1, %2};" : "=l"(d) : "f"(x), "f"(y))
#define UNPACK2(x, y, d) asm("mov.b64 {%0, %1}, %2;" : "=f"(x), "=f"(y) : "l"(d))
#define FMA2(acc, a, b)  asm("fma.rn.f32x2 %0, %1, %2, %0;" : "+l"(acc) : "l"(a), "l"(b))
#define ADD4(a, b)       do { (a).x += (b).x; (a).y += (b).y; (a).z += (b).z; (a).w += (b).w; } while (0)

static __device__ __forceinline__ unsigned pack_h2(float a, float b) {
    __half2 h = __floats2half2_rn(a, b);
    return *reinterpret_cast<unsigned*>(&h);
}
static __device__ __forceinline__ float2 unpack_h2(unsigned u) {
    __half2 h = *reinterpret_cast<__half2*>(&u);
    return __half22float2(h);
}

// ---------------------------------------------------------------- fused phase-1 kernel
// grid = 256 blocks x 256 threads; block owns 32 tokens (4 per warp).
__global__ __launch_bounds__(256, 2) void kF(
    const float* __restrict__ x,
    const float* __restrict__ w_in,   // [14][512]
    const float* __restrict__ b_in,   // [14]
    const float* __restrict__ w_out,  // [512][14]
    const float* __restrict__ b_out,  // [512]
    float* __restrict__ out,
    float* __restrict__ idx_out)
{
    // blob: stage A = s_wout (7280 used); stage C = tA[32][128] | tB[32][128]
    __shared__ __align__(16) float blob[8192];
    __shared__ float s_bin[16];
    __shared__ float sQ[32 * 16];              // p, then sigmoid(p) in place
    __shared__ float sred[16];

    float* s_wout = blob;
    float* tA = blob;
    float* tB = blob + 4096;

    int tid = threadIdx.x;
    for (int i = tid; i < CDIM * DIM; i += 256) {
        int d = i / CDIM, c = i % CDIM;
        s_wout[c * WOPITCH + d] = w_out[i];
    }
    if (tid < CDIM) s_bin[tid] = b_in[tid];
    __syncthreads();

    int w = tid >> 5, l = tid & 31;
    const float4* win4  = (const float4*)w_in;
    const float4* wout4 = (const float4*)s_wout;   // row stride 130 float4
    const float4* bout4 = (const float4*)b_out;

    int tok0   = w * 4;
    int token0 = blockIdx.x * 32 + tok0;

    // ---- stage A part 1: projection, 4 tokens jointly, k-outer
    float s0[CDIM], s1[CDIM], s2[CDIM], s3[CDIM];
    #pragma unroll
    for (int c = 0; c < CDIM; c++) { s0[c]=0.f; s1[c]=0.f; s2[c]=0.f; s3[c]=0.f; }

    #pragma unroll
    for (int k = 0; k < 4; k++) {
        float4 xv0 = ((const float4*)(x + (size_t)(token0    ) * DIM))[k * 32 + l];
        float4 xv1 = ((const float4*)(x + (size_t)(token0 + 1) * DIM))[k * 32 + l];
        float4 xv2 = ((const float4*)(x + (size_t)(token0 + 2) * DIM))[k * 32 + l];
        float4 xv3 = ((const float4*)(x + (size_t)(token0 + 3) * DIM))[k * 32 + l];
        #pragma unroll
        for (int c = 0; c < CDIM; c++) {
            float4 wv = win4[c * 128 + k * 32 + l];
            s0[c] += xv0.x*wv.x + xv0.y*wv.y + xv0.z*wv.z + xv0.w*wv.w;
            s1[c] += xv1.x*wv.x + xv1.y*wv.y + xv1.z*wv.z + xv1.w*wv.w;
            s2[c] += xv2.x*wv.x + xv2.y*wv.y + xv2.z*wv.z + xv2.w*wv.w;
            s3[c] += xv3.x*wv.x + xv3.y*wv.y + xv3.z*wv.z + xv3.w*wv.w;
        }
    }

    // fold reduction: lane group g = l>>3 ends owning token g.
    float pv[CDIM];
    #pragma unroll
    for (int c = 0; c < CDIM; c++) {
        float t0 = s0[c], t1 = s1[c], t2 = s2[c], t3 = s3[c];
        t0 += __shfl_xor_sync(0xffffffffu, t0, 16);
        t1 += __shfl_xor_sync(0xffffffffu, t1, 16);
        t2 += __shfl_xor_sync(0xffffffffu, t2, 16);
        t3 += __shfl_xor_sync(0xffffffffu, t3, 16);
        float a = (l < 16) ? t0 : t2;
        float b = (l < 16) ? t1 : t3;
        a += __shfl_xor_sync(0xffffffffu, a, 8);
        b += __shfl_xor_sync(0xffffffffu, b, 8);
        float m = (l & 8) ? b : a;
        m += __shfl_xor_sync(0xffffffffu, m, 4);
        m += __shfl_xor_sync(0xffffffffu, m, 2);
        m += __shfl_xor_sync(0xffffffffu, m, 1);
        pv[c] = m + s_bin[c];
    }

    int g = l >> 3;
    unsigned idx = 0;
    float commit = 0.f;
    #pragma unroll
    for (int c = 0; c < CDIM; c++) {
        bool pos = pv[c] > 0.f;
        idx |= (pos ? 1u : 0u) << (13 - c);
        float sg = pos ? 1.f : -1.f;
        float d = pv[c] - sg;
        commit += d * d;
    }
    if ((l & 7) == 0) {
        idx_out[token0 + g] = (float)idx;
        #pragma unroll
        for (int c = 0; c < CDIM; c++) sQ[(tok0 + g) * 16 + c] = pv[c];
    }

    unsigned idxs[4];
    #pragma unroll
    for (int t = 0; t < 4; t++) idxs[t] = __shfl_sync(0xffffffffu, idx, t * 8);
    commit += __shfl_xor_sync(0xffffffffu, commit, 8);
    commit += __shfl_xor_sync(0xffffffffu, commit, 16);
    float commit_acc = commit;

    float sg[4][CDIM];
    #pragma unroll
    for (int t = 0; t < 4; t++)
        #pragma unroll
        for (int c = 0; c < CDIM; c++)
            sg[t][c] = ((idxs[t] >> (13 - c)) & 1) ? 1.f : -1.f;

    // ---- stage A part 2: project-out, 4 tokens jointly, k-outer
    #pragma unroll
    for (int k = 0; k < 4; k++) {
        float4 bb = bout4[k * 32 + l];
        float4 a[4];
        #pragma unroll
        for (int t = 0; t < 4; t++) a[t] = bb;
        #pragma unroll
        for (int c = 0; c < CDIM; c++) {
            float4 wv = wout4[c * 130 + k * 32 + l];
            #pragma unroll
            for (int t = 0; t < 4; t++) {
                a[t].x += sg[t][c] * wv.x; a[t].y += sg[t][c] * wv.y;
                a[t].z += sg[t][c] * wv.z; a[t].w += sg[t][c] * wv.w;
            }
        }
        #pragma unroll
        for (int t = 0; t < 4; t++)
            ((float4*)(out + (size_t)(token0 + t) * DIM))[k * 32 + l] = a[t];
    }
    __syncthreads();

    // ---- stage B: sigmoids (in place) + per-sample entropy partial
    float hloc = 0.f;
    for (int i = tid; i < 32 * CDIM; i += 256) {
        int tok = i / CDIM, c = i % CDIM;
        float p = sQ[tok * 16 + c];
        float q = 1.f / (1.f + __expf(-400.f * p));
        sQ[tok * 16 + c] = q;
        float qm = 1.f - q;
        hloc += -(q  * __logf(fmaxf(q,  1e-20f)) +
                  qm * __logf(fmaxf(qm, 1e-20f)));
    }
    __syncthreads();    // q ready; s_wout dead -> blob becomes tables

    // ---- stage C build: all 32 token tables, one pass
    #pragma unroll 1
    for (int t = 0; t < 32; t++) {
        const float4* q4 = (const float4*)&sQ[t * 16];
        if (tid < 128) {                       // A over c = 0..6 (bits 13..7)
            float4 qa = q4[0], qb = q4[1];
            float v = ((tid & 64) ? qa.x : 1.f - qa.x)
                    * ((tid & 32) ? qa.y : 1.f - qa.y)
                    * ((tid & 16) ? qa.z : 1.f - qa.z)
                    * ((tid &  8) ? qa.w : 1.f - qa.w)
                    * ((tid &  4) ? qb.x : 1.f - qb.x)
                    * ((tid &  2) ? qb.y : 1.f - qb.y)
                    * ((tid &  1) ? qb.z : 1.f - qb.z);
            tA[t * 128 + tid] = v;
        } else {                               // B over c = 7..13 (bits 6..0)
            int lo = tid - 128;
            float4 qb = q4[1], qc = q4[2], qd = q4[3];
            float v = ((lo & 64) ? qb.w : 1.f - qb.w)
                    * ((lo & 32) ? qc.x : 1.f - qc.x)
                    * ((lo & 16) ? qc.y : 1.f - qc.y)
                    * ((lo &  8) ? qc.z : 1.f - qc.z)
                    * ((lo &  4) ? qc.w : 1.f - qc.w)
                    * ((lo &  2) ? qd.x : 1.f - qd.x)
                    * ((lo &  1) ? qd.y : 1.f - qd.y);
            tB[t * 128 + lo] = v;
        }
    }
    __syncthreads();

    // ---- stage C consume: barrier-free packed-FFMA2 stream
    unsigned long long acc2[32];
    #pragma unroll
    for (int i = 0; i < 32; i++) acc2[i] = 0ull;

    #pragma unroll 2
    for (int t = 0; t < 32; t++) {
        float4 bv = ((const float4*)&tB[t * 128])[l];         // lane-varying
        unsigned long long bd0, bd1, bd2, bd3;
        PACK2(bd0, bv.x, bv.x); PACK2(bd1, bv.y, bv.y);
        PACK2(bd2, bv.z, bv.z); PACK2(bd3, bv.w, bv.w);
        const float4* ap = (const float4*)&tA[t * 128 + w * 16]; // broadcast
        #pragma unroll
        for (int i2g = 0; i2g < 4; i2g++) {
            float4 aa = ap[i2g];
            unsigned long long ad0, ad1;
            PACK2(ad0, aa.x, aa.y);
            PACK2(ad1, aa.z, aa.w);
            int base = i2g * 8;
            FMA2(acc2[base + 0], ad0, bd0);
            FMA2(acc2[base + 1], ad0, bd1);
            FMA2(acc2[base + 2], ad0, bd2);
            FMA2(acc2[base + 3], ad0, bd3);
            FMA2(acc2[base + 4], ad1, bd0);
            FMA2(acc2[base + 5], ad1, bd1);
            FMA2(acc2[base + 6], ad1, bd2);
            FMA2(acc2[base + 7], ad1, bd3);
        }
    }

    // ---- epilogue: half2 partial writes.
    // Code j = w*2048 + r*128 + l*4 + k; uint2 slot j/4 = w*512 + r*32 + l.
    {
        uint2* dsth = g_parth + (size_t)blockIdx.x * 4096 + w * 512;
        #pragma unroll
        for (int i2 = 0; i2 < 8; i2++) {
            float lo0, hi0, lo1, hi1, lo2, hi2, lo3, hi3;
            UNPACK2(lo0, hi0, acc2[i2 * 4 + 0]);
            UNPACK2(lo1, hi1, acc2[i2 * 4 + 1]);
            UNPACK2(lo2, hi2, acc2[i2 * 4 + 2]);
            UNPACK2(lo3, hi3, acc2[i2 * 4 + 3]);
            uint2 ulo, uhi;
            ulo.x = pack_h2(lo0, lo1); ulo.y = pack_h2(lo2, lo3);
            uhi.x = pack_h2(hi0, hi1); uhi.y = pack_h2(hi2, hi3);
            dsth[(2 * i2    ) * 32 + l] = ulo;
            dsth[(2 * i2 + 1) * 32 + l] = uhi;
        }
    }

    // ---- block scalar partials
    #pragma unroll
    for (int off = 16; off; off >>= 1) hloc += __shfl_xor_sync(0xffffffffu, hloc, off);
    if (l == 0) { sred[w] = commit_acc; sred[8 + w] = hloc; }
    __syncthreads();
    if (tid == 0) {
        float c = 0.f, h = 0.f;
        #pragma unroll
        for (int i = 0; i < 8; i++) { c += sred[i]; h += sred[8 + i]; }
        g_sc[blockIdx.x] = c;
        g_se[blockIdx.x] = h;
    }
}

// ---------------------------------------------------------------- K3: reduce half2 partials -> aux
// grid = 512 blocks x 256 threads. Block bx owns 8 uint2-groups (32 codes).
// Thread: group = bx*8 + (tid&7), chunk = tid>>3 (0..31) sums 8 partials.
// smem combine, entropy on 8 threads, last-block finisher (self-resetting).
__global__ __launch_bounds__(256) void k3(float* __restrict__ aux_out, float inv_ntok) {
    int tid = threadIdx.x;
    int grp   = blockIdx.x * 8 + (tid & 7);       // uint2 group (4 codes)
    int chunk = tid >> 3;                         // 0..31, 8 partials each
    const uint2* ph = g_parth;                    // [partial*4096 + group]
    size_t b0 = (size_t)chunk * 8 * 4096 + grp;

    float4 a0 = make_float4(0,0,0,0), a1 = a0;
    #pragma unroll
    for (int j = 0; j < 8; j += 2) {
        uint2 u0 = ph[b0 + (size_t)(j    ) * 4096];
        uint2 u1 = ph[b0 + (size_t)(j + 1) * 4096];
        float2 f0a = unpack_h2(u0.x), f0b = unpack_h2(u0.y);
        float2 f1a = unpack_h2(u1.x), f1b = unpack_h2(u1.y);
        a0.x += f0a.x; a0.y += f0a.y; a0.z += f0b.x; a0.w += f0b.y;
        a1.x += f1a.x; a1.y += f1a.y; a1.z += f1b.x; a1.w += f1b.y;
    }
    ADD4(a0, a1);

    __shared__ __align__(16) float4 sp[32][8];    // [chunk][group-local]
    sp[chunk][tid & 7] = a0;
    __syncthreads();

    __shared__ float sred[2];
    if (tid < 8) {
        float4 t0 = sp[0][tid];
        #pragma unroll
        for (int c = 1; c < 32; c++) { float4 tt = sp[c][tid]; ADD4(t0, tt); }
        float ax = t0.x * inv_ntok, ay = t0.y * inv_ntok,
              az = t0.z * inv_ntok, aw = t0.w * inv_ntok;
        float s = -(ax * __logf(fmaxf(ax, 1e-20f))
                  + ay * __logf(fmaxf(ay, 1e-20f))
                  + az * __logf(fmaxf(az, 1e-20f))
                  + aw * __logf(fmaxf(aw, 1e-20f)));
        #pragma unroll
        for (int off = 4; off; off >>= 1) s += __shfl_xor_sync(0xffu, s, off);
        if (tid == 0) sred[0] = s;
    }
    __syncthreads();
    if (tid == 0) g_hc[blockIdx.x] = sred[0];

    // last-block-done finisher
    __threadfence();
    __shared__ int lastflag;
    if (tid == 0) lastflag = (atomicAdd(&g_done, 1) == R3BLK - 1);
    __syncthreads();
    if (lastflag) {
        float hc = g_hc[tid] + g_hc[tid + 256];   // R3BLK == 512 entries
        float sc = g_sc[tid];                     // NBLK == 256 entries
        float se = g_se[tid];
        #pragma unroll
        for (int off = 16; off; off >>= 1) {
            hc += __shfl_xor_sync(0xffffffffu, hc, off);
            sc += __shfl_xor_sync(0xffffffffu, sc, off);
            se += __shfl_xor_sync(0xffffffffu, se, off);
        }
        __shared__ float sr[3][8];
        int w = tid >> 5;
        if ((tid & 31) == 0) { sr[0][w] = hc; sr[1][w] = sc; sr[2][w] = se; }
        __syncthreads();
        if (tid == 0) {
            float Hc = 0.f, C = 0.f, Hs = 0.f;
            #pragma unroll
            for (int i = 0; i < 8; i++) { Hc += sr[0][i]; C += sr[1][i]; Hs += sr[2][i]; }
            float per_sample = Hs * inv_ntok;
            float commit = C * inv_ntok * (1.f / (float)CDIM);
            *aux_out = 0.1f * (per_sample - Hc) + 0.25f * commit;
            g_done = 0;                       // reset for next launch/replay
        }
    }
}

// ----------------------------------------------------------------
extern "C" void kernel_launch(void* const* d_in, const int* in_sizes, int n_in,
                              void* d_out, int out_size) {
    const float* x     = (const float*)d_in[0];
    const float* w_in  = (const float*)d_in[1];
    const float* b_in  = (const float*)d_in[2];
    const float* w_out = (const float*)d_in[3];
    const float* b_out = (const float*)d_in[4];

    int ntok = in_sizes[0] / DIM;               // 8192
    float* out     = (float*)d_out;
    float* idx_out = out + (size_t)ntok * DIM;
    float* aux_out = idx_out + ntok;

    kF<<<ntok / 32, 256>>>(x, w_in, b_in, w_out, b_out, out, idx_out);
    k3<<<R3BLK, 256>>>(aux_out, 1.f / (float)ntok);
}